// round 5
// baseline (speedup 1.0000x reference)
#include <cuda_runtime.h>

#define FULLMASK 0xffffffffu

// ---------------- persistent device scratch ----------------
__device__ __align__(16) float g_acc[20000 * 32 * 12];     // 30.7 MB
__device__ float g_ZhS[95 * 32];
__device__ float g_ZhD[95 * 32];
__device__ float g_ptab[95 * 95 * 32];                     // 1.15 MB, L2-hot
__device__ int   g_pidx[200000];
__device__ __align__(16) float4 g_geo[200000];             // (C, vx, vy, vz)

__device__ __forceinline__ void red_add_v4(float* a, float x, float y, float z, float w) {
    asm volatile("red.global.add.v4.f32 [%0], {%1,%2,%3,%4};"
                 :: "l"(a), "f"(x), "f"(y), "f"(z), "f"(w) : "memory");
}
__device__ __forceinline__ void red_add_v2(float* a, float x, float y) {
    asm volatile("red.global.add.v2.f32 [%0], {%1,%2};"
                 :: "l"(a), "f"(x), "f"(y) : "memory");
}
__device__ __forceinline__ float2 ffma2(float2 a, float2 b, float2 c) {
    float2 d;
    asm("fma.rn.f32x2 %0, %1, %2, %3;"
        : "=l"(*(unsigned long long*)&d)
        : "l"(*(unsigned long long*)&a),
          "l"(*(unsigned long long*)&b),
          "l"(*(unsigned long long*)&c));
    return d;
}

// ---------------- tiny precompute kernels ----------------
__global__ void zh_kernel(const float* __restrict__ emb, const float* __restrict__ We2,
                          int ntypes) {
    int t = blockIdx.x;
    if (t >= ntypes) return;
    int u = threadIdx.x & 31;
    int half = threadIdx.x >> 5;
    float s = 0.f;
#pragma unroll 8
    for (int k = 0; k < 32; k++)
        s = fmaf(emb[t * 32 + k], We2[(k + half * 32) * 32 + u], s);
    (half ? g_ZhD : g_ZhS)[t * 32 + u] = s;
}

__global__ __launch_bounds__(256) void ptab_kernel(const float* __restrict__ be2, int ntypes) {
    int w = blockIdx.x * 8 + (threadIdx.x >> 5);
    int npairs = ntypes * ntypes;
    if (w >= npairs) return;
    int u = threadIdx.x & 31;
    int ts = w / ntypes, td = w - ts * ntypes;
    g_ptab[w * 32 + u] = g_ZhS[ts * 32 + u] + g_ZhD[td * 32 + u] + be2[u];
}

__global__ void prep_kernel(const int* __restrict__ src, const int* __restrict__ dst,
                            const int* __restrict__ ntype,
                            const float* __restrict__ bdist, const float* __restrict__ bvec,
                            int N, int E, int ntypes) {
    int stride = gridDim.x * blockDim.x;
    int g = blockIdx.x * blockDim.x + threadIdx.x;
    int n4 = N * 96;
    float4* acc4 = reinterpret_cast<float4*>(g_acc);
    float4 z = make_float4(0.f, 0.f, 0.f, 0.f);
    for (int i = g; i < n4; i += stride) acc4[i] = z;
    for (int e = g; e < E; e += stride) {
        g_pidx[e] = ntype[src[e]] * ntypes + ntype[dst[e]];
        float dd = bdist[e];
        float c = 0.5f * (__cosf(0.62831853071795864769f * dd) + 1.f);
        c = (dd <= 5.0f) ? c : 0.f;
        float bx = bvec[(size_t)e * 3], by = bvec[(size_t)e * 3 + 1], bz = bvec[(size_t)e * 3 + 2];
        float inv = rsqrtf(bx * bx + by * by + bz * bz);
        g_geo[e] = make_float4(c, bx * inv, by * inv, bz * inv);
    }
}

// ---------------- edge phase ----------------
// Warp = 8 edges, lane = channel u. Accumulators packed f32x2 across edge pairs.
// Per-edge scalars (geo, dst) live in lanes 0..7 and are shfl-broadcast in the
// epilogue, keeping mainloop register state ~76 so 3 blocks/SM fit.
__global__ __launch_bounds__(256, 3) void edge_kernel(
    const float* __restrict__ ea, const int* __restrict__ dst,
    const float* __restrict__ Wd1, const float* __restrict__ bd1,
    const float* __restrict__ Wd2, const float* __restrict__ bd2,
    const float* __restrict__ Wd3, const float* __restrict__ bd3,
    const float* __restrict__ We3, const float* __restrict__ be3,
    float* __restrict__ outEF, int E)
{
    __shared__ float2 Wa[64 * 32];   // (Wd1, Wd2)[k][u]
    __shared__ float2 Wb[64 * 32];   // (Wd3, We3)[k][u]
    __shared__ float b1s[32], b2s[32], b3s[32], be3s[32];
    int tid = threadIdx.x;
    for (int i = tid; i < 64 * 32; i += 256) {
        Wa[i] = make_float2(Wd1[i], Wd2[i]);
        Wb[i] = make_float2(Wd3[i], We3[i]);
    }
    if (tid < 32) { b1s[tid] = bd1[tid]; b2s[tid] = bd2[tid]; b3s[tid] = bd3[tid]; be3s[tid] = be3[tid]; }
    __syncthreads();
    const int u = tid & 31;
    int gw = blockIdx.x * 8 + (tid >> 5);
    int nw = gridDim.x * 8;
    int ngroups = (E + 7) >> 3;
    for (int g = gw; g < ngroups; g += nw) {
        int e0 = g * 8;
        // lane-held per-edge scalars (lanes 0..7 own edges e0..e0+7)
        float gC = 0.f, gx = 0.f, gy = 0.f, gz = 0.f;
        int dnl = 0;
        if (u < 8) {
            int e = min(e0 + u, E - 1);
            float4 gg = g_geo[e];
            gC = gg.x; gx = gg.y; gy = gg.z; gz = gg.w;
            dnl = dst[e];
        }
        float a0[8], a1[8], zj[8];
#pragma unroll
        for (int j = 0; j < 8; j++) {
            int e = min(e0 + j, E - 1);
            a0[j] = ea[(size_t)e * 64 + u];
            a1[j] = ea[(size_t)e * 64 + 32 + u];
            zj[j] = g_ptab[(size_t)g_pidx[e] * 32 + u];
        }
        float2 w1[4], w2[4], w3[4], ef[4];
        {
            float b1 = b1s[u], b2 = b2s[u], b3 = b3s[u], be = be3s[u];
#pragma unroll
            for (int p = 0; p < 4; p++) {
                w1[p] = make_float2(b1, b1);
                w2[p] = make_float2(b2, b2);
                w3[p] = make_float2(b3, b3);
                ef[p] = make_float2(be, be);
            }
        }
#pragma unroll 4
        for (int k = 0; k < 32; k++) {
            float2 wa = Wa[k * 32 + u];
            float2 wb = Wb[k * 32 + u];
            float2 d1 = make_float2(wa.x, wa.x);
            float2 d2 = make_float2(wa.y, wa.y);
            float2 d3 = make_float2(wb.x, wb.x);
            float2 de = make_float2(wb.y, wb.y);
#pragma unroll
            for (int p = 0; p < 4; p++) {
                float2 ap;
                ap.x = __shfl_sync(FULLMASK, a0[2 * p], k);
                ap.y = __shfl_sync(FULLMASK, a0[2 * p + 1], k);
                w1[p] = ffma2(ap, d1, w1[p]);
                w2[p] = ffma2(ap, d2, w2[p]);
                w3[p] = ffma2(ap, d3, w3[p]);
                ef[p] = ffma2(ap, de, ef[p]);
            }
        }
#pragma unroll 4
        for (int k = 0; k < 32; k++) {
            float2 wa = Wa[(k + 32) * 32 + u];
            float2 wb = Wb[(k + 32) * 32 + u];
            float2 d1 = make_float2(wa.x, wa.x);
            float2 d2 = make_float2(wa.y, wa.y);
            float2 d3 = make_float2(wb.x, wb.x);
            float2 de = make_float2(wb.y, wb.y);
#pragma unroll
            for (int p = 0; p < 4; p++) {
                float2 ap;
                ap.x = __shfl_sync(FULLMASK, a1[2 * p], k);
                ap.y = __shfl_sync(FULLMASK, a1[2 * p + 1], k);
                w1[p] = ffma2(ap, d1, w1[p]);
                w2[p] = ffma2(ap, d2, w2[p]);
                w3[p] = ffma2(ap, d3, w3[p]);
                ef[p] = ffma2(ap, de, ef[p]);
            }
        }
#pragma unroll
        for (int j = 0; j < 8; j++) {
            int e = e0 + j;
            if (e >= E) break;
            int p = j >> 1;
            float W1 = (j & 1) ? w1[p].y : w1[p].x;
            float W2 = (j & 1) ? w2[p].y : w2[p].x;
            float W3 = (j & 1) ? w3[p].y : w3[p].x;
            float EF = (j & 1) ? ef[p].y : ef[p].x;
            outEF[(size_t)e * 32 + u] = EF;
            float C  = __shfl_sync(FULLMASK, gC, j);
            float vx = __shfl_sync(FULLMASK, gx, j);
            float vy = __shfl_sync(FULLMASK, gy, j);
            float vz = __shfl_sync(FULLMASK, gz, j);
            int  dnj = __shfl_sync(FULLMASK, dnl, j);
            float zc = zj[j] * C;
            float fI = zc * W1;
            float pp = zc * W2;
            float qq = zc * W3;
            float* base = g_acc + ((size_t)dnj * 32 + u) * 12;
            red_add_v4(base,     fI,            pp * vx,       pp * vy,       pp * vz);
            red_add_v4(base + 4, qq * vx * vx,  qq * vy * vy,  qq * vz * vz,  qq * vx * vy);
            red_add_v2(base + 8, qq * vx * vz,  qq * vy * vz);
        }
    }
}

// ---------------- node epilogue ----------------
__global__ __launch_bounds__(256) void node_kernel(
    const float* __restrict__ Ws1, const float* __restrict__ bs1,
    const float* __restrict__ Ws2, const float* __restrict__ bs2,
    const float* __restrict__ Wt0, const float* __restrict__ Wt1, const float* __restrict__ Wt2,
    const float* __restrict__ lng, const float* __restrict__ lnb,
    float* __restrict__ outX, int N)
{
    __shared__ float Ws1s[32 * 64];
    __shared__ float Ws2s[64 * 96];
    __shared__ float Wt0s[32 * 32], Wt1s[32 * 32], Wt2s[32 * 32];
    __shared__ float bs1s[64], bs2s[96], lngs[32], lnbs[32];
    __shared__ float wbuf[8][64];
    int tid = threadIdx.x;
    for (int i = tid; i < 32 * 64; i += 256) Ws1s[i] = Ws1[i];
    for (int i = tid; i < 64 * 96; i += 256) Ws2s[i] = Ws2[i];
    for (int i = tid; i < 32 * 32; i += 256) { Wt0s[i] = Wt0[i]; Wt1s[i] = Wt1[i]; Wt2s[i] = Wt2[i]; }
    if (tid < 64) bs1s[tid] = bs1[tid];
    if (tid < 96) bs2s[tid] = bs2[tid];
    if (tid < 32) { lngs[tid] = lng[tid]; lnbs[tid] = lnb[tid]; }
    __syncthreads();
    const int u = tid & 31, w = tid >> 5;
    float* wb = wbuf[w];
    int gw = blockIdx.x * 8 + w, nw = gridDim.x * 8;
    for (int n = gw; n < N; n += nw) {
        const float* base = g_acc + ((size_t)n * 32 + u) * 12;
        float4 A0 = *reinterpret_cast<const float4*>(base);
        float4 A1 = *reinterpret_cast<const float4*>(base + 4);
        float2 A2 = *reinterpret_cast<const float2*>(base + 8);
        float sI = A0.x, wx = A0.y, wy = A0.z, wz = A0.w;
        float Mxx = A1.x, Myy = A1.y, Mzz = A1.z, Mxy = A1.w, Mxz = A2.x, Myz = A2.y;
        float trM = Mxx + Myy + Mzz;
        float dg = sI - trM * (1.f / 3.f);
        float t00 = dg + Mxx, t11 = dg + Myy, t22 = dg + Mzz;
        float nr = t00 * t00 + t11 * t11 + t22 * t22
                 + 2.f * (Mxy * Mxy + wz * wz + Mxz * Mxz + wy * wy + Myz * Myz + wx * wx);
        float s = nr;
#pragma unroll
        for (int o = 16; o; o >>= 1) s += __shfl_xor_sync(FULLMASK, s, o);
        float mu = s * (1.f / 32.f);
        float dv = nr - mu;
        float v2 = dv * dv;
#pragma unroll
        for (int o = 16; o; o >>= 1) v2 += __shfl_xor_sync(FULLMASK, v2, o);
        float y = dv * rsqrtf(v2 * (1.f / 32.f) + 1e-5f) * lngs[u] + lnbs[u];
        wb[u] = y;
        __syncwarp();
        float h1a = bs1s[u], h1b = bs1s[u + 32];
#pragma unroll 8
        for (int k = 0; k < 32; k++) {
            float t = wb[k];
            h1a = fmaf(t, Ws1s[k * 64 + u], h1a);
            h1b = fmaf(t, Ws1s[k * 64 + u + 32], h1b);
        }
        h1a = h1a / (1.f + __expf(-h1a));
        h1b = h1b / (1.f + __expf(-h1b));
        __syncwarp();
        wb[u] = h1a; wb[u + 32] = h1b;
        __syncwarp();
        float s0 = bs2s[3 * u], s1 = bs2s[3 * u + 1], s2 = bs2s[3 * u + 2];
#pragma unroll 8
        for (int k = 0; k < 64; k++) {
            float t = wb[k];
            s0 = fmaf(t, Ws2s[k * 96 + 3 * u], s0);
            s1 = fmaf(t, Ws2s[k * 96 + 3 * u + 1], s1);
            s2 = fmaf(t, Ws2s[k * 96 + 3 * u + 2], s2);
        }
        s0 = s0 / (1.f + __expf(-s0));
        s1 = s1 / (1.f + __expf(-s1));
        s2 = s2 / (1.f + __expf(-s2));
        float pI = 0, px = 0, py = 0, pz = 0, pxx = 0, pyy = 0, pzz = 0, pxy = 0, pxz = 0, pyz = 0;
#pragma unroll 4
        for (int k = 0; k < 32; k++) {
            float w0v = Wt0s[k * 32 + u], w1v = Wt1s[k * 32 + u], w2v = Wt2s[k * 32 + u];
            pI  = fmaf(__shfl_sync(FULLMASK, sI,  k), w0v, pI);
            px  = fmaf(__shfl_sync(FULLMASK, wx,  k), w1v, px);
            py  = fmaf(__shfl_sync(FULLMASK, wy,  k), w1v, py);
            pz  = fmaf(__shfl_sync(FULLMASK, wz,  k), w1v, pz);
            pxx = fmaf(__shfl_sync(FULLMASK, Mxx, k), w2v, pxx);
            pyy = fmaf(__shfl_sync(FULLMASK, Myy, k), w2v, pyy);
            pzz = fmaf(__shfl_sync(FULLMASK, Mzz, k), w2v, pzz);
            pxy = fmaf(__shfl_sync(FULLMASK, Mxy, k), w2v, pxy);
            pxz = fmaf(__shfl_sync(FULLMASK, Mxz, k), w2v, pxz);
            pyz = fmaf(__shfl_sync(FULLMASK, Myz, k), w2v, pyz);
        }
        float t3 = (pxx + pyy + pzz) * (1.f / 3.f);
        float* o = outX + ((size_t)n * 32 + u) * 9;
        o[0] =  s0 * pI + s2 * (pxx - t3);
        o[1] = -s1 * pz + s2 * pxy;
        o[2] =  s1 * py + s2 * pxz;
        o[3] =  s1 * pz + s2 * pxy;
        o[4] =  s0 * pI + s2 * (pyy - t3);
        o[5] = -s1 * px + s2 * pyz;
        o[6] = -s1 * py + s2 * pxz;
        o[7] =  s1 * px + s2 * pyz;
        o[8] =  s0 * pI + s2 * (pzz - t3);
        __syncwarp();
    }
}

extern "C" void kernel_launch(void* const* d_in, const int* in_sizes, int n_in,
                              void* d_out, int out_size) {
    (void)n_in; (void)out_size;
    const int*   node_type = (const int*)d_in[0];
    const float* edge_attr = (const float*)d_in[1];
    const float* bond_dist = (const float*)d_in[2];
    const float* bond_vec  = (const float*)d_in[3];
    const int*   src = (const int*)d_in[4];
    const int*   dst = (const int*)d_in[5];
    const float* emb = (const float*)d_in[6];
    const float* Wd1 = (const float*)d_in[7];  const float* bd1 = (const float*)d_in[8];
    const float* Wd2 = (const float*)d_in[9];  const float* bd2 = (const float*)d_in[10];
    const float* Wd3 = (const float*)d_in[11]; const float* bd3 = (const float*)d_in[12];
    const float* We2 = (const float*)d_in[13]; const float* be2 = (const float*)d_in[14];
    const float* We3 = (const float*)d_in[15]; const float* be3 = (const float*)d_in[16];
    const float* Wt0 = (const float*)d_in[17];
    const float* Wt1 = (const float*)d_in[18];
    const float* Wt2 = (const float*)d_in[19];
    const float* Ws1 = (const float*)d_in[20]; const float* bs1 = (const float*)d_in[21];
    const float* Ws2 = (const float*)d_in[22]; const float* bs2 = (const float*)d_in[23];
    const float* lng = (const float*)d_in[24]; const float* lnb = (const float*)d_in[25];

    int N = in_sizes[0];
    int E = in_sizes[2];
    int ntypes = in_sizes[6] / 32;
    float* outX  = (float*)d_out;
    float* outEF = outX + (size_t)N * 32 * 9;

    zh_kernel<<<ntypes, 64>>>(emb, We2, ntypes);
    ptab_kernel<<<(ntypes * ntypes + 7) / 8, 256>>>(be2, ntypes);
    prep_kernel<<<1024, 256>>>(src, dst, node_type, bond_dist, bond_vec, N, E, ntypes);
    edge_kernel<<<592, 256>>>(edge_attr, dst, Wd1, bd1, Wd2, bd2, Wd3, bd3,
                              We3, be3, outEF, E);
    node_kernel<<<592, 256>>>(Ws1, bs1, Ws2, bs2, Wt0, Wt1, Wt2, lng, lnb, outX, N);
}

// round 6
// speedup vs baseline: 1.0764x; 1.0764x over previous
#include <cuda_runtime.h>

#define FULLMASK 0xffffffffu

// ---------------- persistent device scratch ----------------
__device__ __align__(16) float g_acc[20000 * 32 * 12];     // 30.7 MB
__device__ float g_ZhS[95 * 32];
__device__ float g_ZhD[95 * 32];
__device__ float g_ptab[95 * 95 * 32];                     // 1.15 MB, L2-hot
__device__ int   g_pidx[200000];
__device__ __align__(16) float4 g_geo[200000];             // (C, vx, vy, vz)

__device__ __forceinline__ void red_add_v4(float* a, float x, float y, float z, float w) {
    asm volatile("red.global.add.v4.f32 [%0], {%1,%2,%3,%4};"
                 :: "l"(a), "f"(x), "f"(y), "f"(z), "f"(w) : "memory");
}
__device__ __forceinline__ void red_add_v2(float* a, float x, float y) {
    asm volatile("red.global.add.v2.f32 [%0], {%1,%2};"
                 :: "l"(a), "f"(x), "f"(y) : "memory");
}
__device__ __forceinline__ float2 ffma2(float2 a, float2 b, float2 c) {
    float2 d;
    asm("fma.rn.f32x2 %0, %1, %2, %3;"
        : "=l"(*(unsigned long long*)&d)
        : "l"(*(unsigned long long*)&a),
          "l"(*(unsigned long long*)&b),
          "l"(*(unsigned long long*)&c));
    return d;
}

// ---------------- tiny precompute kernels ----------------
__global__ void zh_kernel(const float* __restrict__ emb, const float* __restrict__ We2,
                          int ntypes) {
    int t = blockIdx.x;
    if (t >= ntypes) return;
    int u = threadIdx.x & 31;
    int half = threadIdx.x >> 5;
    float s = 0.f;
#pragma unroll 8
    for (int k = 0; k < 32; k++)
        s = fmaf(emb[t * 32 + k], We2[(k + half * 32) * 32 + u], s);
    (half ? g_ZhD : g_ZhS)[t * 32 + u] = s;
}

__global__ __launch_bounds__(256) void ptab_kernel(const float* __restrict__ be2, int ntypes) {
    int w = blockIdx.x * 8 + (threadIdx.x >> 5);
    int npairs = ntypes * ntypes;
    if (w >= npairs) return;
    int u = threadIdx.x & 31;
    int ts = w / ntypes, td = w - ts * ntypes;
    g_ptab[w * 32 + u] = g_ZhS[ts * 32 + u] + g_ZhD[td * 32 + u] + be2[u];
}

__global__ void prep_kernel(const int* __restrict__ src, const int* __restrict__ dst,
                            const int* __restrict__ ntype,
                            const float* __restrict__ bdist, const float* __restrict__ bvec,
                            int N, int E, int ntypes) {
    int stride = gridDim.x * blockDim.x;
    int g = blockIdx.x * blockDim.x + threadIdx.x;
    int n4 = N * 96;
    float4* acc4 = reinterpret_cast<float4*>(g_acc);
    float4 z = make_float4(0.f, 0.f, 0.f, 0.f);
    for (int i = g; i < n4; i += stride) acc4[i] = z;
    for (int e = g; e < E; e += stride) {
        g_pidx[e] = ntype[src[e]] * ntypes + ntype[dst[e]];
        float dd = bdist[e];
        float c = 0.5f * (__cosf(0.62831853071795864769f * dd) + 1.f);
        c = (dd <= 5.0f) ? c : 0.f;
        float bx = bvec[(size_t)e * 3], by = bvec[(size_t)e * 3 + 1], bz = bvec[(size_t)e * 3 + 2];
        float inv = rsqrtf(bx * bx + by * by + bz * bz);
        g_geo[e] = make_float4(c, bx * inv, by * inv, bz * inv);
    }
}

// ---------------- edge phase ----------------
// 512 threads = 16 warps; warp = 8 edges, lane = channel u.
// Inner loop per k: 4 LDS.128 (dup weights + broadcast a-tile) + 16 FFMA2.
// No shuffles, no dup-MOVs. Epilogue scalars staged in smem by lanes 0..7.
struct alignas(16) EdgeSmem {
    float4 Wa4[64 * 32];        // (w1,w1,w2,w2)[k][u]   32 KB
    float4 Wb4[64 * 32];        // (w3,w3,we,we)[k][u]   32 KB
    float  atile[16][64][8];    // per-warp [k][edge]    32 KB
    float4 geos[16][8];         //                        2 KB
    int    dns[16][8];
    int    pids[16][8];
};
static constexpr int EDGE_SMEM = (int)sizeof(EdgeSmem);

__global__ __launch_bounds__(512, 2) void edge_kernel(
    const float* __restrict__ ea, const int* __restrict__ dst,
    const float* __restrict__ Wd1, const float* __restrict__ bd1,
    const float* __restrict__ Wd2, const float* __restrict__ bd2,
    const float* __restrict__ Wd3, const float* __restrict__ bd3,
    const float* __restrict__ We3, const float* __restrict__ be3,
    float* __restrict__ outEF, int E)
{
    extern __shared__ __align__(16) char smraw[];
    EdgeSmem& sm = *reinterpret_cast<EdgeSmem*>(smraw);
    int tid = threadIdx.x;
    for (int i = tid; i < 64 * 32; i += 512) {
        float w1v = Wd1[i], w2v = Wd2[i], w3v = Wd3[i], wev = We3[i];
        sm.Wa4[i] = make_float4(w1v, w1v, w2v, w2v);
        sm.Wb4[i] = make_float4(w3v, w3v, wev, wev);
    }
    __syncthreads();
    const int u = tid & 31, w = tid >> 5;
    const float b1 = bd1[u], b2 = bd2[u], b3 = bd3[u], be = be3[u];
    float* at = &sm.atile[w][0][0];
    int gw = blockIdx.x * 16 + w;
    int nw = gridDim.x * 16;
    int ngroups = (E + 7) >> 3;
    for (int g = gw; g < ngroups; g += nw) {
        int e0 = g * 8;
        __syncwarp();
        // ---- stage: a-tile (transposed via STS.128) + per-edge scalars ----
        {
            float4 A0a, A0b, A1a, A1b;
            float* p0a = &A0a.x; float* p0b = &A0b.x;
            float* p1a = &A1a.x; float* p1b = &A1b.x;
#pragma unroll
            for (int j = 0; j < 4; j++) {
                int e = min(e0 + j, E - 1);
                p0a[j] = ea[(size_t)e * 64 + u];
                p1a[j] = ea[(size_t)e * 64 + 32 + u];
            }
#pragma unroll
            for (int j = 0; j < 4; j++) {
                int e = min(e0 + 4 + j, E - 1);
                p0b[j] = ea[(size_t)e * 64 + u];
                p1b[j] = ea[(size_t)e * 64 + 32 + u];
            }
            *reinterpret_cast<float4*>(at + u * 8)            = A0a;
            *reinterpret_cast<float4*>(at + u * 8 + 4)        = A0b;
            *reinterpret_cast<float4*>(at + (u + 32) * 8)     = A1a;
            *reinterpret_cast<float4*>(at + (u + 32) * 8 + 4) = A1b;
            if (u < 8) {
                int e = min(e0 + u, E - 1);
                sm.geos[w][u] = g_geo[e];
                sm.dns[w][u] = dst[e];
                sm.pids[w][u] = g_pidx[e];
            }
        }
        __syncwarp();
        // ---- GEMV mainloop ----
        float2 w1[4], w2[4], w3[4], ef[4];
#pragma unroll
        for (int p = 0; p < 4; p++) {
            w1[p] = make_float2(b1, b1);
            w2[p] = make_float2(b2, b2);
            w3[p] = make_float2(b3, b3);
            ef[p] = make_float2(be, be);
        }
#pragma unroll 4
        for (int k = 0; k < 64; k++) {
            float4 wa = sm.Wa4[k * 32 + u];   // (w1,w1,w2,w2)
            float4 wb = sm.Wb4[k * 32 + u];   // (w3,w3,we,we)
            float4 aL = *reinterpret_cast<const float4*>(at + k * 8);
            float4 aH = *reinterpret_cast<const float4*>(at + k * 8 + 4);
            float2 d1 = make_float2(wa.x, wa.y);
            float2 d2 = make_float2(wa.z, wa.w);
            float2 d3 = make_float2(wb.x, wb.y);
            float2 de = make_float2(wb.z, wb.w);
            float2 ap0 = make_float2(aL.x, aL.y);
            float2 ap1 = make_float2(aL.z, aL.w);
            float2 ap2 = make_float2(aH.x, aH.y);
            float2 ap3 = make_float2(aH.z, aH.w);
            w1[0] = ffma2(ap0, d1, w1[0]); w2[0] = ffma2(ap0, d2, w2[0]);
            w3[0] = ffma2(ap0, d3, w3[0]); ef[0] = ffma2(ap0, de, ef[0]);
            w1[1] = ffma2(ap1, d1, w1[1]); w2[1] = ffma2(ap1, d2, w2[1]);
            w3[1] = ffma2(ap1, d3, w3[1]); ef[1] = ffma2(ap1, de, ef[1]);
            w1[2] = ffma2(ap2, d1, w1[2]); w2[2] = ffma2(ap2, d2, w2[2]);
            w3[2] = ffma2(ap2, d3, w3[2]); ef[2] = ffma2(ap2, de, ef[2]);
            w1[3] = ffma2(ap3, d1, w1[3]); w2[3] = ffma2(ap3, d2, w2[3]);
            w3[3] = ffma2(ap3, d3, w3[3]); ef[3] = ffma2(ap3, de, ef[3]);
        }
        // ---- epilogue ----
#pragma unroll
        for (int j = 0; j < 8; j++) {
            int e = e0 + j;
            if (e >= E) break;
            int p = j >> 1;
            float W1 = (j & 1) ? w1[p].y : w1[p].x;
            float W2 = (j & 1) ? w2[p].y : w2[p].x;
            float W3 = (j & 1) ? w3[p].y : w3[p].x;
            float EF = (j & 1) ? ef[p].y : ef[p].x;
            outEF[(size_t)e * 32 + u] = EF;
            float4 gg = sm.geos[w][j];
            int dnj = sm.dns[w][j];
            float zj = g_ptab[(size_t)sm.pids[w][j] * 32 + u];
            float C = gg.x, vx = gg.y, vy = gg.z, vz = gg.w;
            float zc = zj * C;
            float fI = zc * W1;
            float pp = zc * W2;
            float qq = zc * W3;
            float* base = g_acc + ((size_t)dnj * 32 + u) * 12;
            red_add_v4(base,     fI,            pp * vx,       pp * vy,       pp * vz);
            red_add_v4(base + 4, qq * vx * vx,  qq * vy * vy,  qq * vz * vz,  qq * vx * vy);
            red_add_v2(base + 8, qq * vx * vz,  qq * vy * vz);
        }
    }
}

// ---------------- node epilogue ----------------
__global__ __launch_bounds__(256) void node_kernel(
    const float* __restrict__ Ws1, const float* __restrict__ bs1,
    const float* __restrict__ Ws2, const float* __restrict__ bs2,
    const float* __restrict__ Wt0, const float* __restrict__ Wt1, const float* __restrict__ Wt2,
    const float* __restrict__ lng, const float* __restrict__ lnb,
    float* __restrict__ outX, int N)
{
    __shared__ float Ws1s[32 * 64];
    __shared__ float Ws2s[64 * 96];
    __shared__ float Wt0s[32 * 32], Wt1s[32 * 32], Wt2s[32 * 32];
    __shared__ float bs1s[64], bs2s[96], lngs[32], lnbs[32];
    __shared__ float wbuf[8][64];
    int tid = threadIdx.x;
    for (int i = tid; i < 32 * 64; i += 256) Ws1s[i] = Ws1[i];
    for (int i = tid; i < 64 * 96; i += 256) Ws2s[i] = Ws2[i];
    for (int i = tid; i < 32 * 32; i += 256) { Wt0s[i] = Wt0[i]; Wt1s[i] = Wt1[i]; Wt2s[i] = Wt2[i]; }
    if (tid < 64) bs1s[tid] = bs1[tid];
    if (tid < 96) bs2s[tid] = bs2[tid];
    if (tid < 32) { lngs[tid] = lng[tid]; lnbs[tid] = lnb[tid]; }
    __syncthreads();
    const int u = tid & 31, w = tid >> 5;
    float* wb = wbuf[w];
    int gw = blockIdx.x * 8 + w, nw = gridDim.x * 8;
    for (int n = gw; n < N; n += nw) {
        const float* base = g_acc + ((size_t)n * 32 + u) * 12;
        float4 A0 = *reinterpret_cast<const float4*>(base);
        float4 A1 = *reinterpret_cast<const float4*>(base + 4);
        float2 A2 = *reinterpret_cast<const float2*>(base + 8);
        float sI = A0.x, wx = A0.y, wy = A0.z, wz = A0.w;
        float Mxx = A1.x, Myy = A1.y, Mzz = A1.z, Mxy = A1.w, Mxz = A2.x, Myz = A2.y;
        float trM = Mxx + Myy + Mzz;
        float dg = sI - trM * (1.f / 3.f);
        float t00 = dg + Mxx, t11 = dg + Myy, t22 = dg + Mzz;
        float nr = t00 * t00 + t11 * t11 + t22 * t22
                 + 2.f * (Mxy * Mxy + wz * wz + Mxz * Mxz + wy * wy + Myz * Myz + wx * wx);
        float s = nr;
#pragma unroll
        for (int o = 16; o; o >>= 1) s += __shfl_xor_sync(FULLMASK, s, o);
        float mu = s * (1.f / 32.f);
        float dv = nr - mu;
        float v2 = dv * dv;
#pragma unroll
        for (int o = 16; o; o >>= 1) v2 += __shfl_xor_sync(FULLMASK, v2, o);
        float y = dv * rsqrtf(v2 * (1.f / 32.f) + 1e-5f) * lngs[u] + lnbs[u];
        wb[u] = y;
        __syncwarp();
        float h1a = bs1s[u], h1b = bs1s[u + 32];
#pragma unroll 8
        for (int k = 0; k < 32; k++) {
            float t = wb[k];
            h1a = fmaf(t, Ws1s[k * 64 + u], h1a);
            h1b = fmaf(t, Ws1s[k * 64 + u + 32], h1b);
        }
        h1a = h1a / (1.f + __expf(-h1a));
        h1b = h1b / (1.f + __expf(-h1b));
        __syncwarp();
        wb[u] = h1a; wb[u + 32] = h1b;
        __syncwarp();
        float s0 = bs2s[3 * u], s1 = bs2s[3 * u + 1], s2 = bs2s[3 * u + 2];
#pragma unroll 8
        for (int k = 0; k < 64; k++) {
            float t = wb[k];
            s0 = fmaf(t, Ws2s[k * 96 + 3 * u], s0);
            s1 = fmaf(t, Ws2s[k * 96 + 3 * u + 1], s1);
            s2 = fmaf(t, Ws2s[k * 96 + 3 * u + 2], s2);
        }
        s0 = s0 / (1.f + __expf(-s0));
        s1 = s1 / (1.f + __expf(-s1));
        s2 = s2 / (1.f + __expf(-s2));
        float pI = 0, px = 0, py = 0, pz = 0, pxx = 0, pyy = 0, pzz = 0, pxy = 0, pxz = 0, pyz = 0;
#pragma unroll 4
        for (int k = 0; k < 32; k++) {
            float w0v = Wt0s[k * 32 + u], w1v = Wt1s[k * 32 + u], w2v = Wt2s[k * 32 + u];
            pI  = fmaf(__shfl_sync(FULLMASK, sI,  k), w0v, pI);
            px  = fmaf(__shfl_sync(FULLMASK, wx,  k), w1v, px);
            py  = fmaf(__shfl_sync(FULLMASK, wy,  k), w1v, py);
            pz  = fmaf(__shfl_sync(FULLMASK, wz,  k), w1v, pz);
            pxx = fmaf(__shfl_sync(FULLMASK, Mxx, k), w2v, pxx);
            pyy = fmaf(__shfl_sync(FULLMASK, Myy, k), w2v, pyy);
            pzz = fmaf(__shfl_sync(FULLMASK, Mzz, k), w2v, pzz);
            pxy = fmaf(__shfl_sync(FULLMASK, Mxy, k), w2v, pxy);
            pxz = fmaf(__shfl_sync(FULLMASK, Mxz, k), w2v, pxz);
            pyz = fmaf(__shfl_sync(FULLMASK, Myz, k), w2v, pyz);
        }
        float t3 = (pxx + pyy + pzz) * (1.f / 3.f);
        float* o = outX + ((size_t)n * 32 + u) * 9;
        o[0] =  s0 * pI + s2 * (pxx - t3);
        o[1] = -s1 * pz + s2 * pxy;
        o[2] =  s1 * py + s2 * pxz;
        o[3] =  s1 * pz + s2 * pxy;
        o[4] =  s0 * pI + s2 * (pyy - t3);
        o[5] = -s1 * px + s2 * pyz;
        o[6] = -s1 * py + s2 * pxz;
        o[7] =  s1 * px + s2 * pyz;
        o[8] =  s0 * pI + s2 * (pzz - t3);
        __syncwarp();
    }
}

extern "C" void kernel_launch(void* const* d_in, const int* in_sizes, int n_in,
                              void* d_out, int out_size) {
    (void)n_in; (void)out_size;
    const int*   node_type = (const int*)d_in[0];
    const float* edge_attr = (const float*)d_in[1];
    const float* bond_dist = (const float*)d_in[2];
    const float* bond_vec  = (const float*)d_in[3];
    const int*   src = (const int*)d_in[4];
    const int*   dst = (const int*)d_in[5];
    const float* emb = (const float*)d_in[6];
    const float* Wd1 = (const float*)d_in[7];  const float* bd1 = (const float*)d_in[8];
    const float* Wd2 = (const float*)d_in[9];  const float* bd2 = (const float*)d_in[10];
    const float* Wd3 = (const float*)d_in[11]; const float* bd3 = (const float*)d_in[12];
    const float* We2 = (const float*)d_in[13]; const float* be2 = (const float*)d_in[14];
    const float* We3 = (const float*)d_in[15]; const float* be3 = (const float*)d_in[16];
    const float* Wt0 = (const float*)d_in[17];
    const float* Wt1 = (const float*)d_in[18];
    const float* Wt2 = (const float*)d_in[19];
    const float* Ws1 = (const float*)d_in[20]; const float* bs1 = (const float*)d_in[21];
    const float* Ws2 = (const float*)d_in[22]; const float* bs2 = (const float*)d_in[23];
    const float* lng = (const float*)d_in[24]; const float* lnb = (const float*)d_in[25];

    int N = in_sizes[0];
    int E = in_sizes[2];
    int ntypes = in_sizes[6] / 32;
    float* outX  = (float*)d_out;
    float* outEF = outX + (size_t)N * 32 * 9;

    cudaFuncSetAttribute(edge_kernel, cudaFuncAttributeMaxDynamicSharedMemorySize, EDGE_SMEM);

    zh_kernel<<<ntypes, 64>>>(emb, We2, ntypes);
    ptab_kernel<<<(ntypes * ntypes + 7) / 8, 256>>>(be2, ntypes);
    prep_kernel<<<1024, 256>>>(src, dst, node_type, bond_dist, bond_vec, N, E, ntypes);
    edge_kernel<<<296, 512, EDGE_SMEM>>>(edge_attr, dst, Wd1, bd1, Wd2, bd2, Wd3, bd3,
                                         We3, be3, outEF, E);
    node_kernel<<<592, 256>>>(Ws1, bs1, Ws2, bs2, Wt0, Wt1, Wt2, lng, lnb, outX, N);
}

// round 7
// speedup vs baseline: 1.2350x; 1.1473x over previous
#include <cuda_runtime.h>

#define FULLMASK 0xffffffffu

// ---------------- persistent device scratch ----------------
// Accumulator component-major: [n][12 comps][32 ch] (10 used, 2 pad)
__device__ __align__(16) float g_acc[20000 * 384];         // 30.7 MB
__device__ float g_ZhS[95 * 32];
__device__ float g_ZhD[95 * 32];
__device__ float g_ptab[95 * 95 * 32];                     // 1.15 MB, L2-hot
__device__ int   g_pidx[200000];
__device__ __align__(16) float4 g_geo[200000];             // (C, vx, vy, vz)

__device__ __forceinline__ void red_add_v2(float* a, float x, float y) {
    asm volatile("red.global.add.v2.f32 [%0], {%1,%2};"
                 :: "l"(a), "f"(x), "f"(y) : "memory");
}
__device__ __forceinline__ float2 ffma2(float2 a, float2 b, float2 c) {
    float2 d;
    asm("fma.rn.f32x2 %0, %1, %2, %3;"
        : "=l"(*(unsigned long long*)&d)
        : "l"(*(unsigned long long*)&a),
          "l"(*(unsigned long long*)&b),
          "l"(*(unsigned long long*)&c));
    return d;
}

// ---------------- tiny precompute kernels ----------------
__global__ void zh_kernel(const float* __restrict__ emb, const float* __restrict__ We2,
                          int ntypes) {
    int t = blockIdx.x;
    if (t >= ntypes) return;
    int u = threadIdx.x & 31;
    int half = threadIdx.x >> 5;
    float s = 0.f;
#pragma unroll 8
    for (int k = 0; k < 32; k++)
        s = fmaf(emb[t * 32 + k], We2[(k + half * 32) * 32 + u], s);
    (half ? g_ZhD : g_ZhS)[t * 32 + u] = s;
}

__global__ __launch_bounds__(256) void ptab_kernel(const float* __restrict__ be2, int ntypes) {
    int w = blockIdx.x * 8 + (threadIdx.x >> 5);
    int npairs = ntypes * ntypes;
    if (w >= npairs) return;
    int u = threadIdx.x & 31;
    int ts = w / ntypes, td = w - ts * ntypes;
    g_ptab[w * 32 + u] = g_ZhS[ts * 32 + u] + g_ZhD[td * 32 + u] + be2[u];
}

__global__ void prep_kernel(const int* __restrict__ src, const int* __restrict__ dst,
                            const int* __restrict__ ntype,
                            const float* __restrict__ bdist, const float* __restrict__ bvec,
                            int N, int E, int ntypes) {
    int stride = gridDim.x * blockDim.x;
    int g = blockIdx.x * blockDim.x + threadIdx.x;
    int n4 = N * 96;   // N*384 floats / 4
    float4* acc4 = reinterpret_cast<float4*>(g_acc);
    float4 z = make_float4(0.f, 0.f, 0.f, 0.f);
    for (int i = g; i < n4; i += stride) acc4[i] = z;
    for (int e = g; e < E; e += stride) {
        g_pidx[e] = ntype[src[e]] * ntypes + ntype[dst[e]];
        float dd = bdist[e];
        float c = 0.5f * (__cosf(0.62831853071795864769f * dd) + 1.f);
        c = (dd <= 5.0f) ? c : 0.f;
        float bx = bvec[(size_t)e * 3], by = bvec[(size_t)e * 3 + 1], bz = bvec[(size_t)e * 3 + 2];
        float inv = rsqrtf(bx * bx + by * by + bz * bz);
        g_geo[e] = make_float4(c, bx * inv, by * inv, bz * inv);
    }
}

// ---------------- edge phase ----------------
// 512 threads = 16 warps; warp = 8 edges. Lane l = (channel pair c=l&15, edge
// half h=l>>4). f32x2 packs channels (2c,2c+1). Weight LDS are half-warp
// broadcast (256B wf); 'a' operands stored pre-duplicated (32B broadcast wf).
// Accumulator is component-major so REDG.v2 wavefronts are 1 line each.
struct alignas(16) EdgeSmem {
    float4 WaP[64 * 16];        // (w1[2c],w1[2c+1],w2[2c],w2[2c+1])[k][c] 16 KB
    float4 WbP[64 * 16];        // (w3.., we..)                            16 KB
    float4 adup[16][64][4];     // per-warp: [k][q]=(a2q,a2q,a2q+1,a2q+1)  64 KB
    float4 geos[16][8];
    int    dns[16][8];
    int    pids[16][8];
};
static constexpr int EDGE_SMEM = (int)sizeof(EdgeSmem);

__global__ __launch_bounds__(512, 2) void edge_kernel(
    const float* __restrict__ ea, const int* __restrict__ dst,
    const float* __restrict__ Wd1, const float* __restrict__ bd1,
    const float* __restrict__ Wd2, const float* __restrict__ bd2,
    const float* __restrict__ Wd3, const float* __restrict__ bd3,
    const float* __restrict__ We3, const float* __restrict__ be3,
    float* __restrict__ outEF, int E)
{
    extern __shared__ __align__(16) char smraw[];
    EdgeSmem& sm = *reinterpret_cast<EdgeSmem*>(smraw);
    int tid = threadIdx.x;
    for (int i = tid; i < 64 * 16; i += 512) {
        int k = i >> 4, c2 = (i & 15) * 2;
        sm.WaP[i] = make_float4(Wd1[k * 32 + c2], Wd1[k * 32 + c2 + 1],
                                Wd2[k * 32 + c2], Wd2[k * 32 + c2 + 1]);
        sm.WbP[i] = make_float4(Wd3[k * 32 + c2], Wd3[k * 32 + c2 + 1],
                                We3[k * 32 + c2], We3[k * 32 + c2 + 1]);
    }
    __syncthreads();
    const int u = tid & 31, w = tid >> 5;
    const int c = u & 15, h = u >> 4;
    const float2 bias1 = make_float2(bd1[2 * c], bd1[2 * c + 1]);
    const float2 bias2 = make_float2(bd2[2 * c], bd2[2 * c + 1]);
    const float2 bias3 = make_float2(bd3[2 * c], bd3[2 * c + 1]);
    const float2 biase = make_float2(be3[2 * c], be3[2 * c + 1]);
    int gw = blockIdx.x * 16 + w;
    int nw = gridDim.x * 16;
    int ngroups = (E + 7) >> 3;
    for (int g = gw; g < ngroups; g += nw) {
        int e0 = g * 8;
        __syncwarp();
        // ---- stage: duplicated a-tile + per-edge scalars ----
        {
            float a0[8], a1[8];
#pragma unroll
            for (int j = 0; j < 8; j++) {
                int e = min(e0 + j, E - 1);
                a0[j] = ea[(size_t)e * 64 + u];
                a1[j] = ea[(size_t)e * 64 + 32 + u];
            }
#pragma unroll
            for (int q = 0; q < 4; q++) {
                sm.adup[w][u][q]      = make_float4(a0[2 * q], a0[2 * q], a0[2 * q + 1], a0[2 * q + 1]);
                sm.adup[w][u + 32][q] = make_float4(a1[2 * q], a1[2 * q], a1[2 * q + 1], a1[2 * q + 1]);
            }
            if (u < 8) {
                int e = min(e0 + u, E - 1);
                sm.geos[w][u] = g_geo[e];
                sm.dns[w][u] = dst[e];
                sm.pids[w][u] = g_pidx[e];
            }
        }
        __syncwarp();
        // ---- GEMV mainloop ----
        float2 w1[4], w2[4], w3[4], ef[4];
#pragma unroll
        for (int j = 0; j < 4; j++) { w1[j] = bias1; w2[j] = bias2; w3[j] = bias3; ef[j] = biase; }
#pragma unroll 4
        for (int k = 0; k < 64; k++) {
            float4 wa = sm.WaP[k * 16 + c];
            float4 wb = sm.WbP[k * 16 + c];
            float4 A = sm.adup[w][k][2 * h];       // edges 4h, 4h+1
            float4 B = sm.adup[w][k][2 * h + 1];   // edges 4h+2, 4h+3
            float2 d1 = make_float2(wa.x, wa.y);
            float2 d2 = make_float2(wa.z, wa.w);
            float2 d3 = make_float2(wb.x, wb.y);
            float2 de = make_float2(wb.z, wb.w);
            float2 ap0 = make_float2(A.x, A.y);
            float2 ap1 = make_float2(A.z, A.w);
            float2 ap2 = make_float2(B.x, B.y);
            float2 ap3 = make_float2(B.z, B.w);
            w1[0] = ffma2(ap0, d1, w1[0]); w2[0] = ffma2(ap0, d2, w2[0]);
            w3[0] = ffma2(ap0, d3, w3[0]); ef[0] = ffma2(ap0, de, ef[0]);
            w1[1] = ffma2(ap1, d1, w1[1]); w2[1] = ffma2(ap1, d2, w2[1]);
            w3[1] = ffma2(ap1, d3, w3[1]); ef[1] = ffma2(ap1, de, ef[1]);
            w1[2] = ffma2(ap2, d1, w1[2]); w2[2] = ffma2(ap2, d2, w2[2]);
            w3[2] = ffma2(ap2, d3, w3[2]); ef[2] = ffma2(ap2, de, ef[2]);
            w1[3] = ffma2(ap3, d1, w1[3]); w2[3] = ffma2(ap3, d2, w2[3]);
            w3[3] = ffma2(ap3, d3, w3[3]); ef[3] = ffma2(ap3, de, ef[3]);
        }
        // ---- epilogue: lane handles channels (2c,2c+1) of edges 4h..4h+3 ----
#pragma unroll
        for (int j = 0; j < 4; j++) {
            int je = 4 * h + j;
            int e = e0 + je;
            if (e >= E) break;
            *reinterpret_cast<float2*>(&outEF[(size_t)e * 32 + 2 * c]) = ef[j];
            float4 gg = sm.geos[w][je];
            int dnj = sm.dns[w][je];
            float2 zj = *reinterpret_cast<const float2*>(&g_ptab[(size_t)sm.pids[w][je] * 32 + 2 * c]);
            float C = gg.x, vx = gg.y, vy = gg.z, vz = gg.w;
            float zcx = zj.x * C, zcy = zj.y * C;
            float fIx = zcx * w1[j].x, fIy = zcy * w1[j].y;
            float px = zcx * w2[j].x, py = zcy * w2[j].y;
            float qx = zcx * w3[j].x, qy = zcy * w3[j].y;
            float* base = g_acc + (size_t)dnj * 384 + 2 * c;
            red_add_v2(base,            fIx,          fIy);
            red_add_v2(base + 32,       px * vx,      py * vx);
            red_add_v2(base + 64,       px * vy,      py * vy);
            red_add_v2(base + 96,       px * vz,      py * vz);
            red_add_v2(base + 128,      qx * vx * vx, qy * vx * vx);
            red_add_v2(base + 160,      qx * vy * vy, qy * vy * vy);
            red_add_v2(base + 192,      qx * vz * vz, qy * vz * vz);
            red_add_v2(base + 224,      qx * vx * vy, qy * vx * vy);
            red_add_v2(base + 256,      qx * vx * vz, qy * vx * vz);
            red_add_v2(base + 288,      qx * vy * vz, qy * vy * vz);
        }
    }
}

// ---------------- node epilogue ----------------
__global__ __launch_bounds__(256) void node_kernel(
    const float* __restrict__ Ws1, const float* __restrict__ bs1,
    const float* __restrict__ Ws2, const float* __restrict__ bs2,
    const float* __restrict__ Wt0, const float* __restrict__ Wt1, const float* __restrict__ Wt2,
    const float* __restrict__ lng, const float* __restrict__ lnb,
    float* __restrict__ outX, int N)
{
    __shared__ float Ws1s[32 * 64];
    __shared__ float Ws2s[64 * 96];
    __shared__ float Wt0s[32 * 32], Wt1s[32 * 32], Wt2s[32 * 32];
    __shared__ float bs1s[64], bs2s[96], lngs[32], lnbs[32];
    __shared__ float wbuf[8][64];
    int tid = threadIdx.x;
    for (int i = tid; i < 32 * 64; i += 256) Ws1s[i] = Ws1[i];
    for (int i = tid; i < 64 * 96; i += 256) Ws2s[i] = Ws2[i];
    for (int i = tid; i < 32 * 32; i += 256) { Wt0s[i] = Wt0[i]; Wt1s[i] = Wt1[i]; Wt2s[i] = Wt2[i]; }
    if (tid < 64) bs1s[tid] = bs1[tid];
    if (tid < 96) bs2s[tid] = bs2[tid];
    if (tid < 32) { lngs[tid] = lng[tid]; lnbs[tid] = lnb[tid]; }
    __syncthreads();
    const int u = tid & 31, w = tid >> 5;
    float* wb = wbuf[w];
    int gw = blockIdx.x * 8 + w, nw = gridDim.x * 8;
    for (int n = gw; n < N; n += nw) {
        const float* base = g_acc + (size_t)n * 384 + u;
        float sI  = base[0];
        float wx  = base[32],  wy  = base[64],  wz  = base[96];
        float Mxx = base[128], Myy = base[160], Mzz = base[192];
        float Mxy = base[224], Mxz = base[256], Myz = base[288];
        float trM = Mxx + Myy + Mzz;
        float dg = sI - trM * (1.f / 3.f);
        float t00 = dg + Mxx, t11 = dg + Myy, t22 = dg + Mzz;
        float nr = t00 * t00 + t11 * t11 + t22 * t22
                 + 2.f * (Mxy * Mxy + wz * wz + Mxz * Mxz + wy * wy + Myz * Myz + wx * wx);
        float s = nr;
#pragma unroll
        for (int o = 16; o; o >>= 1) s += __shfl_xor_sync(FULLMASK, s, o);
        float mu = s * (1.f / 32.f);
        float dv = nr - mu;
        float v2 = dv * dv;
#pragma unroll
        for (int o = 16; o; o >>= 1) v2 += __shfl_xor_sync(FULLMASK, v2, o);
        float y = dv * rsqrtf(v2 * (1.f / 32.f) + 1e-5f) * lngs[u] + lnbs[u];
        wb[u] = y;
        __syncwarp();
        float h1a = bs1s[u], h1b = bs1s[u + 32];
#pragma unroll 8
        for (int k = 0; k < 32; k++) {
            float t = wb[k];
            h1a = fmaf(t, Ws1s[k * 64 + u], h1a);
            h1b = fmaf(t, Ws1s[k * 64 + u + 32], h1b);
        }
        h1a = h1a / (1.f + __expf(-h1a));
        h1b = h1b / (1.f + __expf(-h1b));
        __syncwarp();
        wb[u] = h1a; wb[u + 32] = h1b;
        __syncwarp();
        float s0 = bs2s[3 * u], s1 = bs2s[3 * u + 1], s2 = bs2s[3 * u + 2];
#pragma unroll 8
        for (int k = 0; k < 64; k++) {
            float t = wb[k];
            s0 = fmaf(t, Ws2s[k * 96 + 3 * u], s0);
            s1 = fmaf(t, Ws2s[k * 96 + 3 * u + 1], s1);
            s2 = fmaf(t, Ws2s[k * 96 + 3 * u + 2], s2);
        }
        s0 = s0 / (1.f + __expf(-s0));
        s1 = s1 / (1.f + __expf(-s1));
        s2 = s2 / (1.f + __expf(-s2));
        float pI = 0, px = 0, py = 0, pz = 0, pxx = 0, pyy = 0, pzz = 0, pxy = 0, pxz = 0, pyz = 0;
#pragma unroll 4
        for (int k = 0; k < 32; k++) {
            float w0v = Wt0s[k * 32 + u], w1v = Wt1s[k * 32 + u], w2v = Wt2s[k * 32 + u];
            pI  = fmaf(__shfl_sync(FULLMASK, sI,  k), w0v, pI);
            px  = fmaf(__shfl_sync(FULLMASK, wx,  k), w1v, px);
            py  = fmaf(__shfl_sync(FULLMASK, wy,  k), w1v, py);
            pz  = fmaf(__shfl_sync(FULLMASK, wz,  k), w1v, pz);
            pxx = fmaf(__shfl_sync(FULLMASK, Mxx, k), w2v, pxx);
            pyy = fmaf(__shfl_sync(FULLMASK, Myy, k), w2v, pyy);
            pzz = fmaf(__shfl_sync(FULLMASK, Mzz, k), w2v, pzz);
            pxy = fmaf(__shfl_sync(FULLMASK, Mxy, k), w2v, pxy);
            pxz = fmaf(__shfl_sync(FULLMASK, Mxz, k), w2v, pxz);
            pyz = fmaf(__shfl_sync(FULLMASK, Myz, k), w2v, pyz);
        }
        float t3 = (pxx + pyy + pzz) * (1.f / 3.f);
        float* o = outX + ((size_t)n * 32 + u) * 9;
        o[0] =  s0 * pI + s2 * (pxx - t3);
        o[1] = -s1 * pz + s2 * pxy;
        o[2] =  s1 * py + s2 * pxz;
        o[3] =  s1 * pz + s2 * pxy;
        o[4] =  s0 * pI + s2 * (pyy - t3);
        o[5] = -s1 * px + s2 * pyz;
        o[6] = -s1 * py + s2 * pxz;
        o[7] =  s1 * px + s2 * pyz;
        o[8] =  s0 * pI + s2 * (pzz - t3);
        __syncwarp();
    }
}

extern "C" void kernel_launch(void* const* d_in, const int* in_sizes, int n_in,
                              void* d_out, int out_size) {
    (void)n_in; (void)out_size;
    const int*   node_type = (const int*)d_in[0];
    const float* edge_attr = (const float*)d_in[1];
    const float* bond_dist = (const float*)d_in[2];
    const float* bond_vec  = (const float*)d_in[3];
    const int*   src = (const int*)d_in[4];
    const int*   dst = (const int*)d_in[5];
    const float* emb = (const float*)d_in[6];
    const float* Wd1 = (const float*)d_in[7];  const float* bd1 = (const float*)d_in[8];
    const float* Wd2 = (const float*)d_in[9];  const float* bd2 = (const float*)d_in[10];
    const float* Wd3 = (const float*)d_in[11]; const float* bd3 = (const float*)d_in[12];
    const float* We2 = (const float*)d_in[13]; const float* be2 = (const float*)d_in[14];
    const float* We3 = (const float*)d_in[15]; const float* be3 = (const float*)d_in[16];
    const float* Wt0 = (const float*)d_in[17];
    const float* Wt1 = (const float*)d_in[18];
    const float* Wt2 = (const float*)d_in[19];
    const float* Ws1 = (const float*)d_in[20]; const float* bs1 = (const float*)d_in[21];
    const float* Ws2 = (const float*)d_in[22]; const float* bs2 = (const float*)d_in[23];
    const float* lng = (const float*)d_in[24]; const float* lnb = (const float*)d_in[25];

    int N = in_sizes[0];
    int E = in_sizes[2];
    int ntypes = in_sizes[6] / 32;
    float* outX  = (float*)d_out;
    float* outEF = outX + (size_t)N * 32 * 9;

    cudaFuncSetAttribute(edge_kernel, cudaFuncAttributeMaxDynamicSharedMemorySize, EDGE_SMEM);

    zh_kernel<<<ntypes, 64>>>(emb, We2, ntypes);
    ptab_kernel<<<(ntypes * ntypes + 7) / 8, 256>>>(be2, ntypes);
    prep_kernel<<<1024, 256>>>(src, dst, node_type, bond_dist, bond_vec, N, E, ntypes);
    edge_kernel<<<296, 512, EDGE_SMEM>>>(edge_attr, dst, Wd1, bd1, Wd2, bd2, Wd3, bd3,
                                         We3, be3, outEF, E);
    node_kernel<<<592, 256>>>(Ws1, bs1, Ws2, bs2, Wt0, Wt1, Wt2, lng, lnb, outX, N);
}

// round 9
// speedup vs baseline: 1.3480x; 1.0915x over previous
#include <cuda_runtime.h>

#define FULLMASK 0xffffffffu

// ---------------- persistent device scratch ----------------
// Accumulator component-major: [n][12 comps][32 ch] (10 used, 2 pad never touched)
__device__ __align__(16) float g_acc[20000 * 384];         // 30.7 MB
__device__ float g_ZhS[95 * 32];
__device__ float g_ZhD[95 * 32];
__device__ float g_ptab[95 * 95 * 32];                     // 1.15 MB, L2-hot
__device__ int   g_pidx[200000];
__device__ __align__(16) float4 g_geo[200000];             // (C, vx, vy, vz)

__device__ __forceinline__ void red_add_v2(float* a, float x, float y) {
    asm volatile("red.global.add.v2.f32 [%0], {%1,%2};"
                 :: "l"(a), "f"(x), "f"(y) : "memory");
}
__device__ __forceinline__ float2 ffma2(float2 a, float2 b, float2 c) {
    float2 d;
    asm("fma.rn.f32x2 %0, %1, %2, %3;"
        : "=l"(*(unsigned long long*)&d)
        : "l"(*(unsigned long long*)&a),
          "l"(*(unsigned long long*)&b),
          "l"(*(unsigned long long*)&c));
    return d;
}

// ---------------- tiny precompute kernels ----------------
__global__ void zh_kernel(const float* __restrict__ emb, const float* __restrict__ We2,
                          int ntypes) {
    int t = blockIdx.x;
    if (t >= ntypes) return;
    int u = threadIdx.x & 31;
    int half = threadIdx.x >> 5;
    float s = 0.f;
#pragma unroll 8
    for (int k = 0; k < 32; k++)
        s = fmaf(emb[t * 32 + k], We2[(k + half * 32) * 32 + u], s);
    (half ? g_ZhD : g_ZhS)[t * 32 + u] = s;
}

__global__ __launch_bounds__(256) void ptab_kernel(const float* __restrict__ be2, int ntypes) {
    int w = blockIdx.x * 8 + (threadIdx.x >> 5);
    int npairs = ntypes * ntypes;
    if (w >= npairs) return;
    int u = threadIdx.x & 31;
    int ts = w / ntypes, td = w - ts * ntypes;
    g_ptab[w * 32 + u] = g_ZhS[ts * 32 + u] + g_ZhD[td * 32 + u] + be2[u];
}

__global__ void prep_kernel(const int* __restrict__ src, const int* __restrict__ dst,
                            const int* __restrict__ ntype,
                            const float* __restrict__ bdist, const float* __restrict__ bvec,
                            int N, int E, int ntypes) {
    int stride = gridDim.x * blockDim.x;
    int g = blockIdx.x * blockDim.x + threadIdx.x;
    int n4 = N * 96;   // N*384 floats / 4
    float4* acc4 = reinterpret_cast<float4*>(g_acc);
    float4 z = make_float4(0.f, 0.f, 0.f, 0.f);
    for (int i = g; i < n4; i += stride)
        if ((i % 96) < 80) acc4[i] = z;    // only the 10 used comps
    for (int e = g; e < E; e += stride) {
        g_pidx[e] = ntype[src[e]] * ntypes + ntype[dst[e]];
        float dd = bdist[e];
        float c = 0.5f * (__cosf(0.62831853071795864769f * dd) + 1.f);
        c = (dd <= 5.0f) ? c : 0.f;
        float bx = bvec[(size_t)e * 3], by = bvec[(size_t)e * 3 + 1], bz = bvec[(size_t)e * 3 + 2];
        float inv = rsqrtf(bx * bx + by * by + bz * bz);
        g_geo[e] = make_float4(c, bx * inv, by * inv, bz * inv);
    }
}

// ---------------- edge phase ----------------
// 256 threads = 8 warps; warp = 16 edges. Lane l = (channel pair c=l&15, edge
// half h=l>>4): lane owns channels (2c,2c+1) for edges 8h..8h+7.
// Per k: 2 LDS.128 weights (256B half-warp broadcast) + 4 LDS.128 a-dup
// (32B broadcast) + 32 FFMA2. Weight traffic per edge is HALF of the 8-edge
// version. adup rows padded to 9 float4 (stride 36 words) -> conflict-free STS.
struct alignas(16) EdgeSmem16 {
    float4 WaP[64 * 16];        // (w1[2c],w1[2c+1],w2[2c],w2[2c+1])[k][c] 16 KB
    float4 WbP[64 * 16];        // (w3.., we..)                            16 KB
    float4 adup[8][64][9];      // per-warp [k][q(8 used)+pad]             73.7 KB
    float4 geos[8][16];
    int    dns[8][16];
    int    pids[8][16];
};
static constexpr int EDGE_SMEM = (int)sizeof(EdgeSmem16);

__global__ __launch_bounds__(256, 2) void edge_kernel(
    const float* __restrict__ ea, const int* __restrict__ dst,
    const float* __restrict__ Wd1, const float* __restrict__ bd1,
    const float* __restrict__ Wd2, const float* __restrict__ bd2,
    const float* __restrict__ Wd3, const float* __restrict__ bd3,
    const float* __restrict__ We3, const float* __restrict__ be3,
    float* __restrict__ outEF, int E)
{
    extern __shared__ __align__(16) char smraw[];
    EdgeSmem16& sm = *reinterpret_cast<EdgeSmem16*>(smraw);
    int tid = threadIdx.x;
    for (int i = tid; i < 64 * 16; i += 256) {
        int k = i >> 4, c2 = (i & 15) * 2;
        sm.WaP[i] = make_float4(Wd1[k * 32 + c2], Wd1[k * 32 + c2 + 1],
                                Wd2[k * 32 + c2], Wd2[k * 32 + c2 + 1]);
        sm.WbP[i] = make_float4(Wd3[k * 32 + c2], Wd3[k * 32 + c2 + 1],
                                We3[k * 32 + c2], We3[k * 32 + c2 + 1]);
    }
    __syncthreads();
    const int u = tid & 31, w = tid >> 5;
    const int c = u & 15, h = u >> 4;
    const float2 bias1 = make_float2(bd1[2 * c], bd1[2 * c + 1]);
    const float2 bias2 = make_float2(bd2[2 * c], bd2[2 * c + 1]);
    const float2 bias3 = make_float2(bd3[2 * c], bd3[2 * c + 1]);
    const float2 biase = make_float2(be3[2 * c], be3[2 * c + 1]);
    int gw = blockIdx.x * 8 + w;
    int nw = gridDim.x * 8;
    int ngroups = (E + 15) >> 4;
    for (int g = gw; g < ngroups; g += nw) {
        int e0 = g * 16;
        __syncwarp();
        // ---- stage: duplicated a-tile (lane u owns k-rows u and u+32) ----
        {
            float a0[16], a1[16];
#pragma unroll
            for (int j = 0; j < 16; j++) {
                int e = min(e0 + j, E - 1);
                a0[j] = ea[(size_t)e * 64 + u];
                a1[j] = ea[(size_t)e * 64 + 32 + u];
            }
#pragma unroll
            for (int q = 0; q < 8; q++) {
                sm.adup[w][u][q]      = make_float4(a0[2 * q], a0[2 * q], a0[2 * q + 1], a0[2 * q + 1]);
                sm.adup[w][u + 32][q] = make_float4(a1[2 * q], a1[2 * q], a1[2 * q + 1], a1[2 * q + 1]);
            }
            if (u < 16) {
                int e = min(e0 + u, E - 1);
                sm.geos[w][u] = g_geo[e];
                sm.dns[w][u] = dst[e];
                sm.pids[w][u] = g_pidx[e];
            }
        }
        __syncwarp();
        // ---- GEMV mainloop ----
        float2 w1[8], w2[8], w3[8], ef[8];
#pragma unroll
        for (int j = 0; j < 8; j++) { w1[j] = bias1; w2[j] = bias2; w3[j] = bias3; ef[j] = biase; }
#pragma unroll 2
        for (int k = 0; k < 64; k++) {
            float4 wa = sm.WaP[k * 16 + c];
            float4 wb = sm.WbP[k * 16 + c];
            float4 A0 = sm.adup[w][k][4 * h + 0];
            float4 A1 = sm.adup[w][k][4 * h + 1];
            float4 A2 = sm.adup[w][k][4 * h + 2];
            float4 A3 = sm.adup[w][k][4 * h + 3];
            float2 d1 = make_float2(wa.x, wa.y);
            float2 d2 = make_float2(wa.z, wa.w);
            float2 d3 = make_float2(wb.x, wb.y);
            float2 de = make_float2(wb.z, wb.w);
            float2 ap0 = make_float2(A0.x, A0.y), ap1 = make_float2(A0.z, A0.w);
            float2 ap2 = make_float2(A1.x, A1.y), ap3 = make_float2(A1.z, A1.w);
            float2 ap4 = make_float2(A2.x, A2.y), ap5 = make_float2(A2.z, A2.w);
            float2 ap6 = make_float2(A3.x, A3.y), ap7 = make_float2(A3.z, A3.w);
            w1[0] = ffma2(ap0, d1, w1[0]); w2[0] = ffma2(ap0, d2, w2[0]);
            w3[0] = ffma2(ap0, d3, w3[0]); ef[0] = ffma2(ap0, de, ef[0]);
            w1[1] = ffma2(ap1, d1, w1[1]); w2[1] = ffma2(ap1, d2, w2[1]);
            w3[1] = ffma2(ap1, d3, w3[1]); ef[1] = ffma2(ap1, de, ef[1]);
            w1[2] = ffma2(ap2, d1, w1[2]); w2[2] = ffma2(ap2, d2, w2[2]);
            w3[2] = ffma2(ap2, d3, w3[2]); ef[2] = ffma2(ap2, de, ef[2]);
            w1[3] = ffma2(ap3, d1, w1[3]); w2[3] = ffma2(ap3, d2, w2[3]);
            w3[3] = ffma2(ap3, d3, w3[3]); ef[3] = ffma2(ap3, de, ef[3]);
            w1[4] = ffma2(ap4, d1, w1[4]); w2[4] = ffma2(ap4, d2, w2[4]);
            w3[4] = ffma2(ap4, d3, w3[4]); ef[4] = ffma2(ap4, de, ef[4]);
            w1[5] = ffma2(ap5, d1, w1[5]); w2[5] = ffma2(ap5, d2, w2[5]);
            w3[5] = ffma2(ap5, d3, w3[5]); ef[5] = ffma2(ap5, de, ef[5]);
            w1[6] = ffma2(ap6, d1, w1[6]); w2[6] = ffma2(ap6, d2, w2[6]);
            w3[6] = ffma2(ap6, d3, w3[6]); ef[6] = ffma2(ap6, de, ef[6]);
            w1[7] = ffma2(ap7, d1, w1[7]); w2[7] = ffma2(ap7, d2, w2[7]);
            w3[7] = ffma2(ap7, d3, w3[7]); ef[7] = ffma2(ap7, de, ef[7]);
        }
        // ---- epilogue: lane handles channels (2c,2c+1) of edges 8h+0..7 ----
#pragma unroll
        for (int j = 0; j < 8; j++) {
            int el = 8 * h + j;
            int e = e0 + el;
            if (e < E) {
                *reinterpret_cast<float2*>(&outEF[(size_t)e * 32 + 2 * c]) = ef[j];
                float4 gg = sm.geos[w][el];
                int dnj = sm.dns[w][el];
                float2 zj = *reinterpret_cast<const float2*>(&g_ptab[(size_t)sm.pids[w][el] * 32 + 2 * c]);
                float C = gg.x, vx = gg.y, vy = gg.z, vz = gg.w;
                float zcx = zj.x * C, zcy = zj.y * C;
                float fIx = zcx * w1[j].x, fIy = zcy * w1[j].y;
                float px = zcx * w2[j].x, py = zcy * w2[j].y;
                float qx = zcx * w3[j].x, qy = zcy * w3[j].y;
                float* base = g_acc + (size_t)dnj * 384 + 2 * c;
                red_add_v2(base,       fIx,          fIy);
                red_add_v2(base + 32,  px * vx,      py * vx);
                red_add_v2(base + 64,  px * vy,      py * vy);
                red_add_v2(base + 96,  px * vz,      py * vz);
                red_add_v2(base + 128, qx * vx * vx, qy * vx * vx);
                red_add_v2(base + 160, qx * vy * vy, qy * vy * vy);
                red_add_v2(base + 192, qx * vz * vz, qy * vz * vz);
                red_add_v2(base + 224, qx * vx * vy, qy * vx * vy);
                red_add_v2(base + 256, qx * vx * vz, qy * vx * vz);
                red_add_v2(base + 288, qx * vy * vz, qy * vy * vz);
            }
        }
    }
}

// ---------------- node epilogue ----------------
__global__ __launch_bounds__(256) void node_kernel(
    const float* __restrict__ Ws1, const float* __restrict__ bs1,
    const float* __restrict__ Ws2, const float* __restrict__ bs2,
    const float* __restrict__ Wt0, const float* __restrict__ Wt1, const float* __restrict__ Wt2,
    const float* __restrict__ lng, const float* __restrict__ lnb,
    float* __restrict__ outX, int N)
{
    __shared__ float Ws1s[32 * 64];
    __shared__ float Ws2s[64 * 96];
    __shared__ float Wt0s[32 * 32], Wt1s[32 * 32], Wt2s[32 * 32];
    __shared__ float bs1s[64], bs2s[96], lngs[32], lnbs[32];
    __shared__ float wbuf[8][64];
    int tid = threadIdx.x;
    for (int i = tid; i < 32 * 64; i += 256) Ws1s[i] = Ws1[i];
    for (int i = tid; i < 64 * 96; i += 256) Ws2s[i] = Ws2[i];
    for (int i = tid; i < 32 * 32; i += 256) { Wt0s[i] = Wt0[i]; Wt1s[i] = Wt1[i]; Wt2s[i] = Wt2[i]; }
    if (tid < 64) bs1s[tid] = bs1[tid];
    if (tid < 96) bs2s[tid] = bs2[tid];
    if (tid < 32) { lngs[tid] = lng[tid]; lnbs[tid] = lnb[tid]; }
    __syncthreads();
    const int u = tid & 31, w = tid >> 5;
    float* wb = wbuf[w];
    int gw = blockIdx.x * 8 + w, nw = gridDim.x * 8;
    for (int n = gw; n < N; n += nw) {
        const float* base = g_acc + (size_t)n * 384 + u;
        float sI  = base[0];
        float wx  = base[32],  wy  = base[64],  wz  = base[96];
        float Mxx = base[128], Myy = base[160], Mzz = base[192];
        float Mxy = base[224], Mxz = base[256], Myz = base[288];
        float trM = Mxx + Myy + Mzz;
        float dg = sI - trM * (1.f / 3.f);
        float t00 = dg + Mxx, t11 = dg + Myy, t22 = dg + Mzz;
        float nr = t00 * t00 + t11 * t11 + t22 * t22
                 + 2.f * (Mxy * Mxy + wz * wz + Mxz * Mxz + wy * wy + Myz * Myz + wx * wx);
        float s = nr;
#pragma unroll
        for (int o = 16; o; o >>= 1) s += __shfl_xor_sync(FULLMASK, s, o);
        float mu = s * (1.f / 32.f);
        float dv = nr - mu;
        float v2 = dv * dv;
#pragma unroll
        for (int o = 16; o; o >>= 1) v2 += __shfl_xor_sync(FULLMASK, v2, o);
        float y = dv * rsqrtf(v2 * (1.f / 32.f) + 1e-5f) * lngs[u] + lnbs[u];
        wb[u] = y;
        __syncwarp();
        float h1a = bs1s[u], h1b = bs1s[u + 32];
#pragma unroll 8
        for (int k = 0; k < 32; k++) {
            float t = wb[k];
            h1a = fmaf(t, Ws1s[k * 64 + u], h1a);
            h1b = fmaf(t, Ws1s[k * 64 + u + 32], h1b);
        }
        h1a = h1a / (1.f + __expf(-h1a));
        h1b = h1b / (1.f + __expf(-h1b));
        __syncwarp();
        wb[u] = h1a; wb[u + 32] = h1b;
        __syncwarp();
        float s0 = bs2s[3 * u], s1 = bs2s[3 * u + 1], s2 = bs2s[3 * u + 2];
#pragma unroll 8
        for (int k = 0; k < 64; k++) {
            float t = wb[k];
            s0 = fmaf(t, Ws2s[k * 96 + 3 * u], s0);
            s1 = fmaf(t, Ws2s[k * 96 + 3 * u + 1], s1);
            s2 = fmaf(t, Ws2s[k * 96 + 3 * u + 2], s2);
        }
        s0 = s0 / (1.f + __expf(-s0));
        s1 = s1 / (1.f + __expf(-s1));
        s2 = s2 / (1.f + __expf(-s2));
        float pI = 0, px = 0, py = 0, pz = 0, pxx = 0, pyy = 0, pzz = 0, pxy = 0, pxz = 0, pyz = 0;
#pragma unroll 4
        for (int k = 0; k < 32; k++) {
            float w0v = Wt0s[k * 32 + u], w1v = Wt1s[k * 32 + u], w2v = Wt2s[k * 32 + u];
            pI  = fmaf(__shfl_sync(FULLMASK, sI,  k), w0v, pI);
            px  = fmaf(__shfl_sync(FULLMASK, wx,  k), w1v, px);
            py  = fmaf(__shfl_sync(FULLMASK, wy,  k), w1v, py);
            pz  = fmaf(__shfl_sync(FULLMASK, wz,  k), w1v, pz);
            pxx = fmaf(__shfl_sync(FULLMASK, Mxx, k), w2v, pxx);
            pyy = fmaf(__shfl_sync(FULLMASK, Myy, k), w2v, pyy);
            pzz = fmaf(__shfl_sync(FULLMASK, Mzz, k), w2v, pzz);
            pxy = fmaf(__shfl_sync(FULLMASK, Mxy, k), w2v, pxy);
            pxz = fmaf(__shfl_sync(FULLMASK, Mxz, k), w2v, pxz);
            pyz = fmaf(__shfl_sync(FULLMASK, Myz, k), w2v, pyz);
        }
        float t3 = (pxx + pyy + pzz) * (1.f / 3.f);
        float* o = outX + ((size_t)n * 32 + u) * 9;
        o[0] =  s0 * pI + s2 * (pxx - t3);
        o[1] = -s1 * pz + s2 * pxy;
        o[2] =  s1 * py + s2 * pxz;
        o[3] =  s1 * pz + s2 * pxy;
        o[4] =  s0 * pI + s2 * (pyy - t3);
        o[5] = -s1 * px + s2 * pyz;
        o[6] = -s1 * py + s2 * pxz;
        o[7] =  s1 * px + s2 * pyz;
        o[8] =  s0 * pI + s2 * (pzz - t3);
        __syncwarp();
    }
}

extern "C" void kernel_launch(void* const* d_in, const int* in_sizes, int n_in,
                              void* d_out, int out_size) {
    (void)n_in; (void)out_size;
    const int*   node_type = (const int*)d_in[0];
    const float* edge_attr = (const float*)d_in[1];
    const float* bond_dist = (const float*)d_in[2];
    const float* bond_vec  = (const float*)d_in[3];
    const int*   src = (const int*)d_in[4];
    const int*   dst = (const int*)d_in[5];
    const float* emb = (const float*)d_in[6];
    const float* Wd1 = (const float*)d_in[7];  const float* bd1 = (const float*)d_in[8];
    const float* Wd2 = (const float*)d_in[9];  const float* bd2 = (const float*)d_in[10];
    const float* Wd3 = (const float*)d_in[11]; const float* bd3 = (const float*)d_in[12];
    const float* We2 = (const float*)d_in[13]; const float* be2 = (const float*)d_in[14];
    const float* We3 = (const float*)d_in[15]; const float* be3 = (const float*)d_in[16];
    const float* Wt0 = (const float*)d_in[17];
    const float* Wt1 = (const float*)d_in[18];
    const float* Wt2 = (const float*)d_in[19];
    const float* Ws1 = (const float*)d_in[20]; const float* bs1 = (const float*)d_in[21];
    const float* Ws2 = (const float*)d_in[22]; const float* bs2 = (const float*)d_in[23];
    const float* lng = (const float*)d_in[24]; const float* lnb = (const float*)d_in[25];

    int N = in_sizes[0];
    int E = in_sizes[2];
    int ntypes = in_sizes[6] / 32;
    float* outX  = (float*)d_out;
    float* outEF = outX + (size_t)N * 32 * 9;

    cudaFuncSetAttribute(edge_kernel, cudaFuncAttributeMaxDynamicSharedMemorySize, EDGE_SMEM);

    zh_kernel<<<ntypes, 64>>>(emb, We2, ntypes);
    ptab_kernel<<<(ntypes * ntypes + 7) / 8, 256>>>(be2, ntypes);
    prep_kernel<<<1024, 256>>>(src, dst, node_type, bond_dist, bond_vec, N, E, ntypes);
    edge_kernel<<<592, 256, EDGE_SMEM>>>(edge_attr, dst, Wd1, bd1, Wd2, bd2, Wd3, bd3,
                                         We3, be3, outEF, E);
    node_kernel<<<592, 256>>>(Ws1, bs1, Ws2, bs2, Wt0, Wt1, Wt2, lng, lnb, outX, N);
}